// round 5
// baseline (speedup 1.0000x reference)
#include <cuda_runtime.h>
#include <stdint.h>

// Problem constants (fixed shapes from reference: B=8, K=4, N=131072)
#define T_TOTAL   4194304      // B*K*N
#define TILE      4096         // elements per block
#define NBLK      1024         // T_TOTAL / TILE
#define NT        256          // threads per block
#define NEG_IDLE_F (-100000000.0f)
#define NEG_FILL_F (-1000.0f)

// Decoupled-lookback tile state: [63:62]=status (0 inval,1 agg,2 prefix),
// [61:31]=air sum, [30:0]=surface sum. Self-contained word -> no fences.
__device__ unsigned long long g_state[NBLK];

__global__ void k_init() {
    g_state[blockIdx.x * 256 + threadIdx.x] = 0ULL;
}

__device__ __forceinline__ unsigned long long ld_state(int i) {
    unsigned long long v;
    asm volatile("ld.global.cg.u64 %0, [%1];" : "=l"(v) : "l"(g_state + i));
    return v;
}
__device__ __forceinline__ void st_state(int i, unsigned long long v) {
    asm volatile("st.global.cg.u64 [%0], %1;" :: "l"(g_state + i), "l"(v));
}

// ---------------------------------------------------------------------------
// Fused single-pass kernel: count -> publish agg -> lookback -> expand/write.
// Each thread owns 16 CONTIGUOUS elements (bitmask in one register; per-
// element offsets via popc -> all gather loads independent, full MLP).
// ---------------------------------------------------------------------------
__global__ __launch_bounds__(NT) void k_fused(
    const uint32_t* __restrict__ ms, const uint32_t* __restrict__ ma,
    const float* __restrict__ rgb, const float* __restrict__ ls,
    const float* __restrict__ la,  const float* __restrict__ idle_st,
    float* __restrict__ rgb_out, float* __restrict__ ls_out,
    float* __restrict__ la_out) {

    int blk = blockIdx.x, tid = threadIdx.x;
    int lane = tid & 31, w = tid >> 5;

    size_t e0 = (size_t)blk * TILE + (size_t)tid * 16;
    const uint4* s4 = reinterpret_cast<const uint4*>(ms + e0);
    const uint4* a4 = reinterpret_cast<const uint4*>(ma + e0);

    // Load 16 contiguous mask elems per thread, pack to bit masks.
    unsigned bits_s = 0, bits_a = 0;
    #pragma unroll
    for (int i = 0; i < 4; i++) {
        uint4 s = s4[i];
        uint4 a = a4[i];
        bits_s |= ((s.x != 0u) << (i * 4)) | ((s.y != 0u) << (i * 4 + 1)) |
                  ((s.z != 0u) << (i * 4 + 2)) | ((s.w != 0u) << (i * 4 + 3));
        bits_a |= ((a.x != 0u) << (i * 4)) | ((a.y != 0u) << (i * 4 + 1)) |
                  ((a.z != 0u) << (i * 4 + 2)) | ((a.w != 0u) << (i * 4 + 3));
    }
    int cs = __popc(bits_s), ca = __popc(bits_a);
    int p = cs | (ca << 16);          // packed; per-thread <=16 each, safe

    // Block-wide exclusive scan of packed counts.
    int ip = p;
    #pragma unroll
    for (int o = 1; o < 32; o <<= 1) {
        int t = __shfl_up_sync(0xffffffffu, ip, o);
        if (lane >= o) ip += t;
    }
    __shared__ int wt[8];
    __shared__ int s_run[2];
    if (lane == 31) wt[w] = ip;
    __syncthreads();
    int woff = 0, tot = 0;
    #pragma unroll
    for (int k = 0; k < 8; k++) {
        int v = wt[k];
        if (k < w) woff += v;
        tot += v;
    }
    int ep    = ip - p + woff;        // packed exclusive prefix within tile
    int tot_s = tot & 0xffff, tot_a = tot >> 16;

    // Publish aggregate immediately.
    if (tid == 0) {
        unsigned long long agg = (1ULL << 62) |
            ((unsigned long long)(unsigned)tot_a << 31) | (unsigned)tot_s;
        st_state(blk, agg);
    }

    // Warp-parallel decoupled lookback (warp 0).
    if (w == 0) {
        int rs = 0, ra = 0;
        if (blk > 0) {
            int i = blk - 1;
            for (;;) {
                int j = i - lane;
                unsigned long long v = 0;
                int st = 2;                       // j<0 acts as prefix of 0
                if (j >= 0) { v = ld_state(j); st = (int)(v >> 62); }
                unsigned pending = __ballot_sync(0xffffffffu, st == 0);
                while (pending) {
                    __nanosleep(20);              // backoff: spare L2 from spin reads
                    if (st == 0) { v = ld_state(j); st = (int)(v >> 62); }
                    pending = __ballot_sync(0xffffffffu, st == 0);
                }
                unsigned pmask = __ballot_sync(0xffffffffu, st == 2);
                int take = pmask ? (__ffs(pmask) - 1) : 31;   // lanes 0..take
                int cs_ = 0, ca_ = 0;
                if (lane <= take && (i - lane) >= 0) {
                    cs_ = (int)(v & 0x7fffffffu);
                    ca_ = (int)((v >> 31) & 0x7fffffffu);
                }
                #pragma unroll
                for (int o = 16; o > 0; o >>= 1) {
                    cs_ += __shfl_xor_sync(0xffffffffu, cs_, o);
                    ca_ += __shfl_xor_sync(0xffffffffu, ca_, o);
                }
                rs += cs_; ra += ca_;
                if (pmask) break;
                i -= 32;
            }
        }
        if (lane == 0) {
            s_run[0] = rs; s_run[1] = ra;
            unsigned long long inc = (2ULL << 62) |
                ((unsigned long long)(unsigned)(ra + tot_a) << 31) |
                (unsigned)(rs + tot_s);
            st_state(blk, inc);
        }
    }
    __syncthreads();

    // Per-thread global bases.
    int base_s = s_run[0] + (ep & 0xffff);
    int base_a = s_run[1] + (ep >> 16);

    float idle   = idle_st[blk >> 5];   // 32 tiles per (b,k) row
    float scale  = 1.0f - idle;
    float negadd = idle * NEG_IDLE_F;

    // Expand + write. 4 groups of 4 elems; all gather loads independent.
    #pragma unroll
    for (int g = 0; g < 4; g++) {
        float os[4], oa[4], ro[12];
        #pragma unroll
        for (int qq = 0; qq < 4; qq++) {
            int q = g * 4 + qq;
            if ((bits_s >> q) & 1) {
                int idx = base_s + __popc(bits_s & ((1u << q) - 1u));
                os[qq] = __ldg(ls + idx) * scale + negadd;
                const float* rp = rgb + (size_t)idx * 3;
                ro[qq * 3 + 0] = rp[0] * scale;
                ro[qq * 3 + 1] = rp[1] * scale;
                ro[qq * 3 + 2] = rp[2] * scale;
            } else {
                os[qq] = NEG_FILL_F;
                ro[qq * 3 + 0] = 0.0f; ro[qq * 3 + 1] = 0.0f; ro[qq * 3 + 2] = 0.0f;
            }
            if ((bits_a >> q) & 1) {
                int idx = base_a + __popc(bits_a & ((1u << q) - 1u));
                oa[qq] = __ldg(la + idx) * scale + negadd;
            } else {
                oa[qq] = NEG_FILL_F;
            }
        }
        size_t eg = e0 + g * 4;
        *reinterpret_cast<float4*>(ls_out + eg) = make_float4(os[0], os[1], os[2], os[3]);
        *reinterpret_cast<float4*>(la_out + eg) = make_float4(oa[0], oa[1], oa[2], oa[3]);
        float4* rout = reinterpret_cast<float4*>(rgb_out + eg * 3);
        rout[0] = make_float4(ro[0], ro[1],  ro[2],  ro[3]);
        rout[1] = make_float4(ro[4], ro[5],  ro[6],  ro[7]);
        rout[2] = make_float4(ro[8], ro[9],  ro[10], ro[11]);
    }
}

// ---------------------------------------------------------------------------
// Launch: 2 kernels (state init + fused single-pass). Graph-capturable.
// ---------------------------------------------------------------------------
extern "C" void kernel_launch(void* const* d_in, const int* in_sizes, int n_in,
                              void* d_out, int out_size) {
    const float*    rgb  = (const float*)d_in[0];
    const float*    ls   = (const float*)d_in[1];
    const float*    la   = (const float*)d_in[2];
    const uint32_t* msf  = (const uint32_t*)d_in[3];
    const uint32_t* maf  = (const uint32_t*)d_in[4];
    const float*    idle = (const float*)d_in[5];

    float* out     = (float*)d_out;
    float* rgb_out = out;
    float* ls_out  = out + (size_t)T_TOTAL * 3;
    float* la_out  = ls_out + T_TOTAL;

    k_init<<<NBLK / 256, 256>>>();
    k_fused<<<NBLK, NT>>>(msf, maf, rgb, ls, la, idle, rgb_out, ls_out, la_out);
}

// round 7
// speedup vs baseline: 1.0038x; 1.0038x over previous
#include <cuda_runtime.h>
#include <stdint.h>

// Problem constants (fixed shapes from reference: B=8, K=4, N=131072)
#define T_TOTAL   4194304      // B*K*N
#define TILE      4096         // elements per block
#define NBLK      1024         // T_TOTAL / TILE
#define NT        256          // threads per block
#define NEG_IDLE_F (-100000000.0f)
#define NEG_FILL_F (-1000.0f)

// Scratch (device globals — no allocation allowed in kernel_launch)
__device__ int      g_sum_s[NBLK];
__device__ int      g_sum_a[NBLK];
__device__ int      g_off_s[NBLK];
__device__ int      g_off_a[NBLK];
__device__ unsigned g_packed[T_TOTAL / 16];   // 1MB: 16 surf bits | 16 air bits

// ---------------------------------------------------------------------------
// Kernel 1: read both masks once, bit-pack to 1MB scratch, compute tile sums.
// Each thread owns 16 CONTIGUOUS elements of each mask.
// ---------------------------------------------------------------------------
__global__ __launch_bounds__(NT) void k_pack(const uint32_t* __restrict__ ms,
                                             const uint32_t* __restrict__ ma) {
    int blk = blockIdx.x, tid = threadIdx.x;
    size_t e0 = (size_t)blk * TILE + (size_t)tid * 16;
    const uint4* s4 = reinterpret_cast<const uint4*>(ms + e0);
    const uint4* a4 = reinterpret_cast<const uint4*>(ma + e0);

    unsigned bits_s = 0, bits_a = 0;
    #pragma unroll
    for (int i = 0; i < 4; i++) {
        uint4 s = s4[i];
        uint4 a = a4[i];
        bits_s |= ((s.x != 0u) << (i * 4)) | ((s.y != 0u) << (i * 4 + 1)) |
                  ((s.z != 0u) << (i * 4 + 2)) | ((s.w != 0u) << (i * 4 + 3));
        bits_a |= ((a.x != 0u) << (i * 4)) | ((a.y != 0u) << (i * 4 + 1)) |
                  ((a.z != 0u) << (i * 4 + 2)) | ((a.w != 0u) << (i * 4 + 3));
    }
    g_packed[blk * NT + tid] = bits_s | (bits_a << 16);

    // Packed per-thread counts (each field <= 16; block total <= 4096 < 2^16).
    int p = __popc(bits_s) | (__popc(bits_a) << 16);
    #pragma unroll
    for (int o = 16; o > 0; o >>= 1)
        p += __shfl_xor_sync(0xffffffffu, p, o);

    __shared__ int sh[8];
    int w = tid >> 5;
    if ((tid & 31) == 0) sh[w] = p;
    __syncthreads();
    if (tid == 0) {
        int t = 0;
        #pragma unroll
        for (int i = 0; i < 8; i++) t += sh[i];
        g_sum_s[blk] = t & 0xffff;
        g_sum_a[blk] = t >> 16;
    }
}

// ---------------------------------------------------------------------------
// Kernel 2: exclusive scan of the 1024 tile sums (one block, 1024 threads)
// ---------------------------------------------------------------------------
__global__ __launch_bounds__(1024) void k_scan() {
    int tid = threadIdx.x, lane = tid & 31, w = tid >> 5;
    int vs = g_sum_s[tid], va = g_sum_a[tid];
    int is = vs, ia = va;
    #pragma unroll
    for (int o = 1; o < 32; o <<= 1) {
        int t = __shfl_up_sync(0xffffffffu, is, o); if (lane >= o) is += t;
        t     = __shfl_up_sync(0xffffffffu, ia, o); if (lane >= o) ia += t;
    }
    __shared__ int ws[32], wa[32];
    if (lane == 31) { ws[w] = is; wa[w] = ia; }
    __syncthreads();
    if (w == 0) {
        int ts = ws[lane], ta = wa[lane];
        int js = ts, ja = ta;
        #pragma unroll
        for (int o = 1; o < 32; o <<= 1) {
            int t = __shfl_up_sync(0xffffffffu, js, o); if (lane >= o) js += t;
            t     = __shfl_up_sync(0xffffffffu, ja, o); if (lane >= o) ja += t;
        }
        ws[lane] = js - ts;   // exclusive warp offsets
        wa[lane] = ja - ta;
    }
    __syncthreads();
    g_off_s[tid] = ws[w] + is - vs;
    g_off_a[tid] = wa[w] + ia - va;
}

// ---------------------------------------------------------------------------
// Kernel 3: expand/gather/write from packed bits (1MB, L2-hot).
// Per-element offsets via popc -> all gather loads independent (full MLP).
// ---------------------------------------------------------------------------
__global__ __launch_bounds__(NT) void k_main(
    const float* __restrict__ rgb, const float* __restrict__ ls,
    const float* __restrict__ la,  const float* __restrict__ idle_st,
    float* __restrict__ rgb_out, float* __restrict__ ls_out,
    float* __restrict__ la_out) {

    int blk = blockIdx.x, tid = threadIdx.x;
    int lane = tid & 31, w = tid >> 5;

    unsigned pk = g_packed[blk * NT + tid];
    unsigned bits_s = pk & 0xffffu, bits_a = pk >> 16;

    // Block-wide exclusive scan of packed counts.
    int p = __popc(bits_s) | (__popc(bits_a) << 16);
    int ip = p;
    #pragma unroll
    for (int o = 1; o < 32; o <<= 1) {
        int t = __shfl_up_sync(0xffffffffu, ip, o);
        if (lane >= o) ip += t;
    }
    __shared__ int wt[8];
    if (lane == 31) wt[w] = ip;
    __syncthreads();
    int woff = 0;
    #pragma unroll
    for (int k = 0; k < 8; k++)
        if (k < w) woff += wt[k];
    int ep = ip - p + woff;           // packed exclusive prefix within tile

    int base_s = g_off_s[blk] + (ep & 0xffff);
    int base_a = g_off_a[blk] + (ep >> 16);

    float idle   = idle_st[blk >> 5];  // 32 tiles per (b,k) row
    float scale  = 1.0f - idle;
    float negadd = idle * NEG_IDLE_F;

    size_t e0 = (size_t)blk * TILE + (size_t)tid * 16;

    #pragma unroll
    for (int g = 0; g < 4; g++) {
        float os[4], oa[4], ro[12];
        #pragma unroll
        for (int qq = 0; qq < 4; qq++) {
            int q = g * 4 + qq;
            if ((bits_s >> q) & 1) {
                int idx = base_s + __popc(bits_s & ((1u << q) - 1u));
                os[qq] = __ldg(ls + idx) * scale + negadd;
                const float* rp = rgb + (size_t)idx * 3;
                ro[qq * 3 + 0] = rp[0] * scale;
                ro[qq * 3 + 1] = rp[1] * scale;
                ro[qq * 3 + 2] = rp[2] * scale;
            } else {
                os[qq] = NEG_FILL_F;
                ro[qq * 3 + 0] = 0.0f; ro[qq * 3 + 1] = 0.0f; ro[qq * 3 + 2] = 0.0f;
            }
            if ((bits_a >> q) & 1) {
                int idx = base_a + __popc(bits_a & ((1u << q) - 1u));
                oa[qq] = __ldg(la + idx) * scale + negadd;
            } else {
                oa[qq] = NEG_FILL_F;
            }
        }
        size_t eg = e0 + g * 4;
        *reinterpret_cast<float4*>(ls_out + eg) = make_float4(os[0], os[1], os[2], os[3]);
        *reinterpret_cast<float4*>(la_out + eg) = make_float4(oa[0], oa[1], oa[2], oa[3]);
        float4* rout = reinterpret_cast<float4*>(rgb_out + eg * 3);
        rout[0] = make_float4(ro[0], ro[1],  ro[2],  ro[3]);
        rout[1] = make_float4(ro[4], ro[5],  ro[6],  ro[7]);
        rout[2] = make_float4(ro[8], ro[9],  ro[10], ro[11]);
    }
}

// ---------------------------------------------------------------------------
// Launch: 3 kernels (pack+count, scan, expand). Graph-capturable.
// ---------------------------------------------------------------------------
extern "C" void kernel_launch(void* const* d_in, const int* in_sizes, int n_in,
                              void* d_out, int out_size) {
    const float*    rgb  = (const float*)d_in[0];
    const float*    ls   = (const float*)d_in[1];
    const float*    la   = (const float*)d_in[2];
    const uint32_t* msf  = (const uint32_t*)d_in[3];
    const uint32_t* maf  = (const uint32_t*)d_in[4];
    const float*    idle = (const float*)d_in[5];

    float* out     = (float*)d_out;
    float* rgb_out = out;
    float* ls_out  = out + (size_t)T_TOTAL * 3;
    float* la_out  = ls_out + T_TOTAL;

    k_pack<<<NBLK, NT>>>(msf, maf);
    k_scan<<<1, 1024>>>();
    k_main<<<NBLK, NT>>>(rgb, ls, la, idle, rgb_out, ls_out, la_out);
}

// round 10
// speedup vs baseline: 1.4909x; 1.4853x over previous
#include <cuda_runtime.h>
#include <stdint.h>

// Problem constants (fixed shapes from reference: B=8, K=4, N=131072)
#define T_TOTAL   4194304      // B*K*N
#define TILE      4096         // elements per block
#define NBLK      1024         // T_TOTAL / TILE
#define NT        256          // threads per block
#define NEG_IDLE_F (-100000000.0f)
#define NEG_FILL_F (-1000.0f)

// Scratch (device globals — no allocation allowed in kernel_launch)
__device__ int      g_sum_s[NBLK];
__device__ int      g_sum_a[NBLK];
__device__ int      g_off_s[NBLK];
__device__ int      g_off_a[NBLK];
__device__ unsigned g_packed[T_TOTAL / 16];   // 1MB: 16 surf bits | 16 air bits

// ---------------------------------------------------------------------------
// Kernel 1: read both masks once, bit-pack to 1MB scratch, compute tile sums.
// Each thread owns 16 CONTIGUOUS elements of each mask. (measured 9.6us)
// ---------------------------------------------------------------------------
__global__ __launch_bounds__(NT) void k_pack(const uint32_t* __restrict__ ms,
                                             const uint32_t* __restrict__ ma) {
    int blk = blockIdx.x, tid = threadIdx.x;
    size_t e0 = (size_t)blk * TILE + (size_t)tid * 16;
    const uint4* s4 = reinterpret_cast<const uint4*>(ms + e0);
    const uint4* a4 = reinterpret_cast<const uint4*>(ma + e0);

    unsigned bits_s = 0, bits_a = 0;
    #pragma unroll
    for (int i = 0; i < 4; i++) {
        uint4 s = s4[i];
        uint4 a = a4[i];
        bits_s |= ((s.x != 0u) << (i * 4)) | ((s.y != 0u) << (i * 4 + 1)) |
                  ((s.z != 0u) << (i * 4 + 2)) | ((s.w != 0u) << (i * 4 + 3));
        bits_a |= ((a.x != 0u) << (i * 4)) | ((a.y != 0u) << (i * 4 + 1)) |
                  ((a.z != 0u) << (i * 4 + 2)) | ((a.w != 0u) << (i * 4 + 3));
    }
    g_packed[blk * NT + tid] = bits_s | (bits_a << 16);

    // Packed per-thread counts (each field <= 16; block total <= 4096 < 2^16).
    int p = __popc(bits_s) | (__popc(bits_a) << 16);
    #pragma unroll
    for (int o = 16; o > 0; o >>= 1)
        p += __shfl_xor_sync(0xffffffffu, p, o);

    __shared__ int sh[8];
    int w = tid >> 5;
    if ((tid & 31) == 0) sh[w] = p;
    __syncthreads();
    if (tid == 0) {
        int t = 0;
        #pragma unroll
        for (int i = 0; i < 8; i++) t += sh[i];
        g_sum_s[blk] = t & 0xffff;
        g_sum_a[blk] = t >> 16;
    }
}

// ---------------------------------------------------------------------------
// Kernel 2: exclusive scan of the 1024 tile sums (one block, 1024 threads)
// ---------------------------------------------------------------------------
__global__ __launch_bounds__(1024) void k_scan() {
    int tid = threadIdx.x, lane = tid & 31, w = tid >> 5;
    int vs = g_sum_s[tid], va = g_sum_a[tid];
    int is = vs, ia = va;
    #pragma unroll
    for (int o = 1; o < 32; o <<= 1) {
        int t = __shfl_up_sync(0xffffffffu, is, o); if (lane >= o) is += t;
        t     = __shfl_up_sync(0xffffffffu, ia, o); if (lane >= o) ia += t;
    }
    __shared__ int ws[32], wa[32];
    if (lane == 31) { ws[w] = is; wa[w] = ia; }
    __syncthreads();
    if (w == 0) {
        int ts = ws[lane], ta = wa[lane];
        int js = ts, ja = ta;
        #pragma unroll
        for (int o = 1; o < 32; o <<= 1) {
            int t = __shfl_up_sync(0xffffffffu, js, o); if (lane >= o) js += t;
            t     = __shfl_up_sync(0xffffffffu, ja, o); if (lane >= o) ja += t;
        }
        ws[lane] = js - ts;   // exclusive warp offsets
        wa[lane] = ja - ta;
    }
    __syncthreads();
    g_off_s[tid] = ws[w] + is - vs;
    g_off_a[tid] = wa[w] + ia - va;
}

// ---------------------------------------------------------------------------
// Kernel 3: expand/gather/write — R2's proven coalesced layout (4 contiguous
// elems/thread/iter, 4 iters) but mask bits come from the 1MB packed scratch
// (one word broadcast to 4 threads) and gather offsets via popc (independent
// loads, no serial idx++ chain).
// ---------------------------------------------------------------------------
__global__ __launch_bounds__(NT) void k_main(
    const float* __restrict__ rgb, const float* __restrict__ ls,
    const float* __restrict__ la,  const float* __restrict__ idle_st,
    float* __restrict__ rgb_out, float* __restrict__ ls_out,
    float* __restrict__ la_out) {

    int blk = blockIdx.x, tid = threadIdx.x;
    int lane = tid & 31, w = tid >> 5;

    float idle   = idle_st[blk >> 5];  // 32 tiles per (b,k) row
    float scale  = 1.0f - idle;
    float negadd = idle * NEG_IDLE_F;

    int run_s = g_off_s[blk];
    int run_a = g_off_a[blk];

    __shared__ int shp[2][8];

    #pragma unroll
    for (int j = 0; j < 4; j++) {
        int e0 = blk * TILE + j * (NT * 4) + tid * 4;
        // word covers 16 elems; 4 threads share it (L1 broadcast)
        unsigned word  = g_packed[(unsigned)e0 >> 4];
        unsigned shift = (tid & 3) * 4;
        unsigned ms4 = (word >> shift) & 0xFu;
        unsigned ma4 = (word >> (16 + shift)) & 0xFu;

        int p = __popc(ms4) | (__popc(ma4) << 16);

        // inclusive warp scan of packed counts
        int ip = p;
        #pragma unroll
        for (int o = 1; o < 32; o <<= 1) {
            int t = __shfl_up_sync(0xffffffffu, ip, o);
            if (lane >= o) ip += t;
        }
        if (lane == 31) shp[j & 1][w] = ip;   // warp total (packed)
        __syncthreads();

        int woff = 0, tot = 0;
        #pragma unroll
        for (int k = 0; k < 8; k++) {
            int v = shp[j & 1][k];
            if (k < w) woff += v;
            tot += v;
        }
        int ep     = ip - p + woff;     // exclusive packed prefix in this chunk
        int base_s = run_s + (ep & 0xffff);
        int base_a = run_a + (ep >> 16);
        run_s += (tot & 0xffff);
        run_a += (tot >> 16);

        float outl_s[4], outl_a[4], ro[12];

        #pragma unroll
        for (int q = 0; q < 4; q++) {
            if ((ms4 >> q) & 1u) {
                int idx = base_s + __popc(ms4 & ((1u << q) - 1u));
                outl_s[q] = __ldg(ls + idx) * scale + negadd;
                const float* rp = rgb + (size_t)idx * 3;
                ro[q * 3 + 0] = rp[0] * scale;
                ro[q * 3 + 1] = rp[1] * scale;
                ro[q * 3 + 2] = rp[2] * scale;
            } else {
                outl_s[q] = NEG_FILL_F;
                ro[q * 3 + 0] = 0.0f; ro[q * 3 + 1] = 0.0f; ro[q * 3 + 2] = 0.0f;
            }
            if ((ma4 >> q) & 1u) {
                int idx = base_a + __popc(ma4 & ((1u << q) - 1u));
                outl_a[q] = __ldg(la + idx) * scale + negadd;
            } else {
                outl_a[q] = NEG_FILL_F;
            }
        }

        // Coalesced 16B stores; e0 is a multiple of 4 -> all float4 aligned.
        *reinterpret_cast<float4*>(ls_out + e0) =
            make_float4(outl_s[0], outl_s[1], outl_s[2], outl_s[3]);
        *reinterpret_cast<float4*>(la_out + e0) =
            make_float4(outl_a[0], outl_a[1], outl_a[2], outl_a[3]);
        float4* rout = reinterpret_cast<float4*>(rgb_out + (size_t)e0 * 3);
        rout[0] = make_float4(ro[0], ro[1],  ro[2],  ro[3]);
        rout[1] = make_float4(ro[4], ro[5],  ro[6],  ro[7]);
        rout[2] = make_float4(ro[8], ro[9],  ro[10], ro[11]);
    }
}

// ---------------------------------------------------------------------------
// Launch: 3 kernels (pack+count, scan, expand). Graph-capturable.
// ---------------------------------------------------------------------------
extern "C" void kernel_launch(void* const* d_in, const int* in_sizes, int n_in,
                              void* d_out, int out_size) {
    const float*    rgb  = (const float*)d_in[0];
    const float*    ls   = (const float*)d_in[1];
    const float*    la   = (const float*)d_in[2];
    const uint32_t* msf  = (const uint32_t*)d_in[3];
    const uint32_t* maf  = (const uint32_t*)d_in[4];
    const float*    idle = (const float*)d_in[5];

    float* out     = (float*)d_out;
    float* rgb_out = out;
    float* ls_out  = out + (size_t)T_TOTAL * 3;
    float* la_out  = ls_out + T_TOTAL;

    k_pack<<<NBLK, NT>>>(msf, maf);
    k_scan<<<1, 1024>>>();
    k_main<<<NBLK, NT>>>(rgb, ls, la, idle, rgb_out, ls_out, la_out);
}